// round 15
// baseline (speedup 1.0000x reference)
#include <cuda_runtime.h>
#include <cuda_fp16.h>
#include <stdint.h>

namespace ode {

// RK4, 2 internal steps (dt=1/2), fused affine maps:
//   Wc = W_in@Wf, bc = b_in@Wf + bf  ->  z0 = x@Wc + bc directly
//   Wio = W_in@W_out, bio = b_in@W_out + b_out
//   out = x@Wio + D@W_out + bio, D = y1 - y0 (fp32 delta state)
// Main loop: f32 MUFU tanh + f32 combine (R14 showed f16 tanh LENGTHENS the
// critical chain: loop is chain-latency balanced at max(tensor,MUFU), and
// pack/unpack ops on the chain starve the tensor pipe). Prep kernel stages
// weights to SMEM coalesced (R14's fix, -18us of graph critical path).
constexpr int NSTEPS = 2;

__device__ uint2 gWfHi[4][8][32];     // hi-only Wf B-fragments (main loop)
__device__ uint4 gWcTab[8][32];       // Wc  hi/lo fragments (z0)
__device__ uint4 gWioTab[2][32];      // Wio hi/lo fragments (epilogue)
__device__ uint4 gWoutTab[4][2][32];  // W_out hi/lo fragments (epilogue)
__device__ float gbc[64];
__device__ float gbio[16];

__device__ __forceinline__ uint32_t pack_h2(float lo, float hi) {
    __half2 h = __floats2half2_rn(lo, hi);
    return *reinterpret_cast<uint32_t*>(&h);
}
__device__ __forceinline__ float h_lo(uint32_t p) {
    __half2 h = *reinterpret_cast<__half2*>(&p);
    return __half2float(__low2half(h));
}
__device__ __forceinline__ float h_hi(uint32_t p) {
    __half2 h = *reinterpret_cast<__half2*>(&p);
    return __half2float(__high2half(h));
}
__device__ __forceinline__ float tanh_fast(float x) {
    float r;
    asm("tanh.approx.f32 %0, %1;" : "=f"(r) : "f"(x));
    return r;
}
__device__ __forceinline__ void mma_f16(float& c0, float& c1, float& c2, float& c3,
                                        uint32_t a0, uint32_t a1, uint32_t a2, uint32_t a3,
                                        uint32_t b0, uint32_t b1) {
    asm volatile(
        "mma.sync.aligned.m16n8k16.row.col.f32.f16.f16.f32 "
        "{%0,%1,%2,%3}, {%4,%5,%6,%7}, {%8,%9}, {%0,%1,%2,%3};"
        : "+f"(c0), "+f"(c1), "+f"(c2), "+f"(c3)
        : "r"(a0), "r"(a1), "r"(a2), "r"(a3), "r"(b0), "r"(b1));
}

__device__ __forceinline__ uint4 make_frag(float w00, float w01, float w10, float w11) {
    uint32_t bh0 = pack_h2(w00, w01);
    uint32_t bh1 = pack_h2(w10, w11);
    uint4 v;
    v.x = bh0;
    v.y = bh1;
    v.z = pack_h2(w00 - h_lo(bh0), w01 - h_hi(bh0));
    v.w = pack_h2(w10 - h_lo(bh1), w11 - h_hi(bh1));
    return v;
}

// Prep kernel: one CTA. Stages all weights to SMEM (coalesced), then computes
// fused fp32 matrices + all fragment tables from SMEM.
__global__ void prep_tables(const float* __restrict__ Wf,
                            const float* __restrict__ W_in,
                            const float* __restrict__ b_in,
                            const float* __restrict__ bfv,
                            const float* __restrict__ W_out,
                            const float* __restrict__ b_out) {
    __shared__ float sWf[64 * 64];
    __shared__ float sWin[16 * 64];
    __shared__ float sWo[64 * 16];
    __shared__ float sWc[16 * 64];
    __shared__ float sWio[16 * 16];
    const int tid  = threadIdx.x;
    const int lane = tid & 31;
    const int w    = tid >> 5;
    const int g    = lane >> 2;
    const int lam  = lane & 3;

    // coalesced staging
    {
        const float4* wf4 = reinterpret_cast<const float4*>(Wf);
        float4* s4 = reinterpret_cast<float4*>(sWf);
        #pragma unroll
        for (int i = 0; i < 8; ++i) s4[tid + i * 128] = wf4[tid + i * 128];
        const float4* wi4 = reinterpret_cast<const float4*>(W_in);
        float4* si4 = reinterpret_cast<float4*>(sWin);
        #pragma unroll
        for (int i = 0; i < 2; ++i) si4[tid + i * 128] = wi4[tid + i * 128];
        const float4* wo4 = reinterpret_cast<const float4*>(W_out);
        float4* so4 = reinterpret_cast<float4*>(sWo);
        #pragma unroll
        for (int i = 0; i < 2; ++i) so4[tid + i * 128] = wo4[tid + i * 128];
    }
    __syncthreads();

    // Wc[i][j] = sum_k W_in[i][k] * Wf[k][j]   (fp32, from SMEM)
    for (int e = tid; e < 16 * 64; e += 128) {
        const int i = e >> 6, j = e & 63;
        float acc = 0.0f;
        #pragma unroll 8
        for (int k = 0; k < 64; ++k) acc = fmaf(sWin[i * 64 + k], sWf[k * 64 + j], acc);
        sWc[e] = acc;
    }
    // Wio[i][j] = sum_k W_in[i][k] * W_out[k][j]
    for (int e = tid; e < 16 * 16; e += 128) {
        const int i = e >> 4, j = e & 15;
        float acc = 0.0f;
        #pragma unroll 8
        for (int k = 0; k < 64; ++k) acc = fmaf(sWin[i * 64 + k], sWo[k * 16 + j], acc);
        sWio[e] = acc;
    }
    // bc = b_in @ Wf + bf ; bio = b_in @ W_out + b_out
    if (tid < 64) {
        float acc = bfv[tid];
        #pragma unroll 8
        for (int i = 0; i < 64; ++i) acc = fmaf(b_in[i], sWf[i * 64 + tid], acc);
        gbc[tid] = acc;
    } else if (tid < 80) {
        const int j = tid - 64;
        float acc = b_out[j];
        #pragma unroll 8
        for (int i = 0; i < 64; ++i) acc = fmaf(b_in[i], sWo[i * 16 + j], acc);
        gbio[j] = acc;
    }
    __syncthreads();

    if (w == 0) {
        #pragma unroll
        for (int nt = 0; nt < 8; ++nt) {
            const int col = nt * 8 + g;
            gWcTab[nt][lane] = make_frag(sWc[(lam * 2) * 64 + col],
                                         sWc[(lam * 2 + 1) * 64 + col],
                                         sWc[(lam * 2 + 8) * 64 + col],
                                         sWc[(lam * 2 + 9) * 64 + col]);
        }
    } else if (w == 1) {
        #pragma unroll
        for (int nt = 0; nt < 2; ++nt) {
            const int col = nt * 8 + g;
            gWioTab[nt][lane] = make_frag(sWio[(lam * 2) * 16 + col],
                                          sWio[(lam * 2 + 1) * 16 + col],
                                          sWio[(lam * 2 + 8) * 16 + col],
                                          sWio[(lam * 2 + 9) * 16 + col]);
        }
    } else if (w == 2) {
        #pragma unroll
        for (int kt = 0; kt < 4; ++kt)
            #pragma unroll
            for (int nt = 0; nt < 2; ++nt) {
                const int col = nt * 8 + g;
                const int kr  = kt * 16 + lam * 2;
                gWoutTab[kt][nt][lane] = make_frag(sWo[kr * 16 + col],
                                                   sWo[(kr + 1) * 16 + col],
                                                   sWo[(kr + 8) * 16 + col],
                                                   sWo[(kr + 9) * 16 + col]);
            }
    } else {
        #pragma unroll
        for (int kt = 0; kt < 4; ++kt)
            #pragma unroll
            for (int nt = 0; nt < 8; ++nt) {
                const int base = (kt * 16 + lam * 2) * 64 + nt * 8 + g;
                uint2 t;
                t.x = pack_h2(sWf[base], sWf[base + 64]);
                t.y = pack_h2(sWf[base + 8 * 64], sWf[base + 9 * 64]);
                gWfHi[kt][nt][lane] = t;
            }
    }
}

__global__ void __launch_bounds__(128, 2)
ode_rk4(const float* __restrict__ x, float* __restrict__ out) {
    __shared__ float sbc[64];
    __shared__ float sbio[16];

    const int tid  = threadIdx.x;
    const int lane = tid & 31;
    const int warp = tid >> 5;
    const int g    = lane >> 2;
    const int lam  = lane & 3;
    const long rowbase = (long)blockIdx.x * 64;
    const int r0 = warp * 16 + g;

    if (tid < 64) sbc[tid] = gbc[tid];
    if (tid < 16) sbio[tid] = gbio[tid];
    __syncthreads();

    // ---- x A-fragments (direct LDG.64), fp16 hi/lo split; live whole kernel ----
    const float* xr0 = x + (rowbase + r0) * 16 + 2 * lam;
    const float* xr8 = x + (rowbase + r0 + 8) * 16 + 2 * lam;
    float2 xa = *reinterpret_cast<const float2*>(xr0);
    float2 xb = *reinterpret_cast<const float2*>(xr8);
    float2 xc = *reinterpret_cast<const float2*>(xr0 + 8);
    float2 xd = *reinterpret_cast<const float2*>(xr8 + 8);
    uint32_t xh0 = pack_h2(xa.x, xa.y), xh1 = pack_h2(xb.x, xb.y);
    uint32_t xh2 = pack_h2(xc.x, xc.y), xh3 = pack_h2(xd.x, xd.y);
    uint32_t xl0 = pack_h2(xa.x - h_lo(xh0), xa.y - h_hi(xh0));
    uint32_t xl1 = pack_h2(xb.x - h_lo(xh1), xb.y - h_hi(xh1));
    uint32_t xl2 = pack_h2(xc.x - h_lo(xh2), xc.y - h_hi(xh2));
    uint32_t xl3 = pack_h2(xd.x - h_lo(xh3), xd.y - h_hi(xh3));

    // ---- z0 = x @ Wc + bc  (fused; 3 MMAs per n-tile) ----
    float z[8][4];
    #pragma unroll
    for (int nt = 0; nt < 8; ++nt) {
        uint4 wt = gWcTab[nt][lane];
        const float2 bb = *reinterpret_cast<const float2*>(&sbc[nt * 8 + lam * 2]);
        float c0 = bb.x, c1 = bb.y, c2 = bb.x, c3 = bb.y;
        mma_f16(c0, c1, c2, c3, xh0, xh1, xh2, xh3, wt.x, wt.y);
        mma_f16(c0, c1, c2, c3, xh0, xh1, xh2, xh3, wt.z, wt.w);
        mma_f16(c0, c1, c2, c3, xl0, xl1, xl2, xl3, wt.x, wt.y);
        z[nt][0] = c0; z[nt][1] = c1; z[nt][2] = c2; z[nt][3] = c3;
    }

    // ---- Wf hi fragments for the loop ----
    uint32_t Bh[4][8][2];
    #pragma unroll
    for (int kt = 0; kt < 4; ++kt)
        #pragma unroll
        for (int nt = 0; nt < 8; ++nt) {
            uint2 t = gWfHi[kt][nt][lane];
            Bh[kt][nt][0] = t.x;
            Bh[kt][nt][1] = t.y;
        }

    // ---- RK4 main loop (delta form); D accumulates y1 - y0 in fp32 ----
    const float DT   = 1.0f / 2.0f;
    const float DT6  = DT / 6.0f;
    const float CMID[3] = {DT * 0.5f, DT * 0.5f, DT};
    const float SW[3]   = {2.0f, 2.0f, 1.0f};

    float D[8][4];
    #pragma unroll
    for (int nt = 0; nt < 8; ++nt) {
        D[nt][0] = 0.f; D[nt][1] = 0.f; D[nt][2] = 0.f; D[nt][3] = 0.f;
    }

    float s[8][4];
    uint32_t a[4][4], an[4][4];

    #pragma unroll
    for (int step = 0; step < NSTEPS; ++step) {
        #pragma unroll
        for (int nt = 0; nt < 8; ++nt) {
            float k0 = tanh_fast(z[nt][0]);
            float k1 = tanh_fast(z[nt][1]);
            float k2 = tanh_fast(z[nt][2]);
            float k3 = tanh_fast(z[nt][3]);
            s[nt][0] = k0; s[nt][1] = k1; s[nt][2] = k2; s[nt][3] = k3;
            const int kt2 = nt >> 1, sl = (nt & 1) * 2;
            a[kt2][sl]     = pack_h2(CMID[0] * k0, CMID[0] * k1);
            a[kt2][sl + 1] = pack_h2(CMID[0] * k2, CMID[0] * k3);
        }
        #pragma unroll
        for (int e = 0; e < 3; ++e) {
            const float sw = SW[e];
            const float cm = (e < 2) ? CMID[e + 1] : 0.0f;
            #pragma unroll
            for (int nt = 0; nt < 8; ++nt) {
                float c0 = z[nt][0], c1 = z[nt][1], c2 = z[nt][2], c3 = z[nt][3];
                #pragma unroll
                for (int kt = 0; kt < 4; ++kt)
                    mma_f16(c0, c1, c2, c3,
                            a[kt][0], a[kt][1], a[kt][2], a[kt][3],
                            Bh[kt][nt][0], Bh[kt][nt][1]);
                c0 = tanh_fast(c0); c1 = tanh_fast(c1);
                c2 = tanh_fast(c2); c3 = tanh_fast(c3);
                s[nt][0] = fmaf(sw, c0, s[nt][0]);
                s[nt][1] = fmaf(sw, c1, s[nt][1]);
                s[nt][2] = fmaf(sw, c2, s[nt][2]);
                s[nt][3] = fmaf(sw, c3, s[nt][3]);
                if (e < 2) {
                    const int kt2 = nt >> 1, sl = (nt & 1) * 2;
                    an[kt2][sl]     = pack_h2(cm * c0, cm * c1);
                    an[kt2][sl + 1] = pack_h2(cm * c2, cm * c3);
                }
            }
            if (e < 2) {
                #pragma unroll
                for (int kt = 0; kt < 4; ++kt) {
                    a[kt][0] = an[kt][0]; a[kt][1] = an[kt][1];
                    a[kt][2] = an[kt][2]; a[kt][3] = an[kt][3];
                }
            }
        }
        #pragma unroll
        for (int nt = 0; nt < 8; ++nt) {
            float u0 = DT6 * s[nt][0], u1 = DT6 * s[nt][1];
            float u2 = DT6 * s[nt][2], u3 = DT6 * s[nt][3];
            D[nt][0] += u0; D[nt][1] += u1; D[nt][2] += u2; D[nt][3] += u3;
            const int kt2 = nt >> 1, sl = (nt & 1) * 2;
            a[kt2][sl]     = pack_h2(u0, u1);
            a[kt2][sl + 1] = pack_h2(u2, u3);
        }
        if (step < NSTEPS - 1) {
            #pragma unroll
            for (int nt = 0; nt < 8; ++nt) {
                #pragma unroll
                for (int kt = 0; kt < 4; ++kt)
                    mma_f16(z[nt][0], z[nt][1], z[nt][2], z[nt][3],
                            a[kt][0], a[kt][1], a[kt][2], a[kt][3],
                            Bh[kt][nt][0], Bh[kt][nt][1]);
            }
        }
    }

    // ---- readout: out = x@Wio + D@W_out + bio, direct STG ----
    {
        uint32_t ah[4][4], al[4][4];
        #pragma unroll
        for (int kt = 0; kt < 4; ++kt) {
            const int nA = 2 * kt, nB = 2 * kt + 1;
            ah[kt][0] = pack_h2(D[nA][0], D[nA][1]);
            ah[kt][1] = pack_h2(D[nA][2], D[nA][3]);
            ah[kt][2] = pack_h2(D[nB][0], D[nB][1]);
            ah[kt][3] = pack_h2(D[nB][2], D[nB][3]);
            al[kt][0] = pack_h2(D[nA][0] - h_lo(ah[kt][0]), D[nA][1] - h_hi(ah[kt][0]));
            al[kt][1] = pack_h2(D[nA][2] - h_lo(ah[kt][1]), D[nA][3] - h_hi(ah[kt][1]));
            al[kt][2] = pack_h2(D[nB][0] - h_lo(ah[kt][2]), D[nB][1] - h_hi(ah[kt][2]));
            al[kt][3] = pack_h2(D[nB][2] - h_lo(ah[kt][3]), D[nB][3] - h_hi(ah[kt][3]));
        }
        #pragma unroll
        for (int nt = 0; nt < 2; ++nt) {
            const float2 bb = *reinterpret_cast<const float2*>(&sbio[nt * 8 + lam * 2]);
            float c0 = bb.x, c1 = bb.y, c2 = bb.x, c3 = bb.y;
            uint4 wio = gWioTab[nt][lane];
            mma_f16(c0, c1, c2, c3, xh0, xh1, xh2, xh3, wio.x, wio.y);
            mma_f16(c0, c1, c2, c3, xh0, xh1, xh2, xh3, wio.z, wio.w);
            mma_f16(c0, c1, c2, c3, xl0, xl1, xl2, xl3, wio.x, wio.y);
            #pragma unroll
            for (int kt = 0; kt < 4; ++kt) {
                uint4 wt = gWoutTab[kt][nt][lane];
                mma_f16(c0, c1, c2, c3, ah[kt][0], ah[kt][1], ah[kt][2], ah[kt][3],
                        wt.x, wt.y);
                mma_f16(c0, c1, c2, c3, ah[kt][0], ah[kt][1], ah[kt][2], ah[kt][3],
                        wt.z, wt.w);
                mma_f16(c0, c1, c2, c3, al[kt][0], al[kt][1], al[kt][2], al[kt][3],
                        wt.x, wt.y);
            }
            float2* o0 = reinterpret_cast<float2*>(out + (rowbase + r0) * 16 + nt * 8 + 2 * lam);
            float2* o8 = reinterpret_cast<float2*>(out + (rowbase + r0 + 8) * 16 + nt * 8 + 2 * lam);
            *o0 = make_float2(c0, c1);
            *o8 = make_float2(c2, c3);
        }
    }
}

}  // namespace ode

extern "C" void kernel_launch(void* const* d_in, const int* in_sizes, int n_in,
                              void* d_out, int out_size) {
    const float* x     = (const float*)d_in[0];
    const float* W_in  = (const float*)d_in[1];
    const float* b_in  = (const float*)d_in[2];
    const float* Wf    = (const float*)d_in[3];
    const float* bfv   = (const float*)d_in[4];
    const float* W_out = (const float*)d_in[5];
    const float* b_out = (const float*)d_in[6];
    float* out = (float*)d_out;

    const int batch = in_sizes[0] / 16;
    const int grid  = batch / 64;
    ode::prep_tables<<<1, 128>>>(Wf, W_in, b_in, bfv, W_out, b_out);
    ode::ode_rk4<<<grid, 128>>>(x, out);
}

// round 16
// speedup vs baseline: 1.5100x; 1.5100x over previous
#include <cuda_runtime.h>
#include <cuda_fp16.h>
#include <stdint.h>

namespace ode {

// RK4, 2 internal steps (dt=1/2), fused affine maps:
//   Wc = W_in@Wf, bc = b_in@Wf + bf  ->  z0 = x@Wc + bc directly
//   Wio = W_in@W_out, bio = b_in@W_out + b_out
//   out = x@Wio + D@W_out + bio, D = y1 - y0 (fp32 delta state)
// Main loop: f32 MUFU tanh + f32 combine. Prep kernel stages weights to SMEM.
// R16 = identical resubmission of R15 to re-measure: R15's 320us ncu reading
// showed unchanged pipe %s and cycle-identical SASS vs R13's 211us -> DVFS
// clock artifact, not a code effect. rel_err must reproduce 9.584441e-5.
constexpr int NSTEPS = 2;

__device__ uint2 gWfHi[4][8][32];     // hi-only Wf B-fragments (main loop)
__device__ uint4 gWcTab[8][32];       // Wc  hi/lo fragments (z0)
__device__ uint4 gWioTab[2][32];      // Wio hi/lo fragments (epilogue)
__device__ uint4 gWoutTab[4][2][32];  // W_out hi/lo fragments (epilogue)
__device__ float gbc[64];
__device__ float gbio[16];

__device__ __forceinline__ uint32_t pack_h2(float lo, float hi) {
    __half2 h = __floats2half2_rn(lo, hi);
    return *reinterpret_cast<uint32_t*>(&h);
}
__device__ __forceinline__ float h_lo(uint32_t p) {
    __half2 h = *reinterpret_cast<__half2*>(&p);
    return __half2float(__low2half(h));
}
__device__ __forceinline__ float h_hi(uint32_t p) {
    __half2 h = *reinterpret_cast<__half2*>(&p);
    return __half2float(__high2half(h));
}
__device__ __forceinline__ float tanh_fast(float x) {
    float r;
    asm("tanh.approx.f32 %0, %1;" : "=f"(r) : "f"(x));
    return r;
}
__device__ __forceinline__ void mma_f16(float& c0, float& c1, float& c2, float& c3,
                                        uint32_t a0, uint32_t a1, uint32_t a2, uint32_t a3,
                                        uint32_t b0, uint32_t b1) {
    asm volatile(
        "mma.sync.aligned.m16n8k16.row.col.f32.f16.f16.f32 "
        "{%0,%1,%2,%3}, {%4,%5,%6,%7}, {%8,%9}, {%0,%1,%2,%3};"
        : "+f"(c0), "+f"(c1), "+f"(c2), "+f"(c3)
        : "r"(a0), "r"(a1), "r"(a2), "r"(a3), "r"(b0), "r"(b1));
}

__device__ __forceinline__ uint4 make_frag(float w00, float w01, float w10, float w11) {
    uint32_t bh0 = pack_h2(w00, w01);
    uint32_t bh1 = pack_h2(w10, w11);
    uint4 v;
    v.x = bh0;
    v.y = bh1;
    v.z = pack_h2(w00 - h_lo(bh0), w01 - h_hi(bh0));
    v.w = pack_h2(w10 - h_lo(bh1), w11 - h_hi(bh1));
    return v;
}

// Prep kernel: one CTA. Stages all weights to SMEM (coalesced), then computes
// fused fp32 matrices + all fragment tables from SMEM.
__global__ void prep_tables(const float* __restrict__ Wf,
                            const float* __restrict__ W_in,
                            const float* __restrict__ b_in,
                            const float* __restrict__ bfv,
                            const float* __restrict__ W_out,
                            const float* __restrict__ b_out) {
    __shared__ float sWf[64 * 64];
    __shared__ float sWin[16 * 64];
    __shared__ float sWo[64 * 16];
    __shared__ float sWc[16 * 64];
    __shared__ float sWio[16 * 16];
    const int tid  = threadIdx.x;
    const int lane = tid & 31;
    const int w    = tid >> 5;
    const int g    = lane >> 2;
    const int lam  = lane & 3;

    // coalesced staging
    {
        const float4* wf4 = reinterpret_cast<const float4*>(Wf);
        float4* s4 = reinterpret_cast<float4*>(sWf);
        #pragma unroll
        for (int i = 0; i < 8; ++i) s4[tid + i * 128] = wf4[tid + i * 128];
        const float4* wi4 = reinterpret_cast<const float4*>(W_in);
        float4* si4 = reinterpret_cast<float4*>(sWin);
        #pragma unroll
        for (int i = 0; i < 2; ++i) si4[tid + i * 128] = wi4[tid + i * 128];
        const float4* wo4 = reinterpret_cast<const float4*>(W_out);
        float4* so4 = reinterpret_cast<float4*>(sWo);
        #pragma unroll
        for (int i = 0; i < 2; ++i) so4[tid + i * 128] = wo4[tid + i * 128];
    }
    __syncthreads();

    // Wc[i][j] = sum_k W_in[i][k] * Wf[k][j]   (fp32, from SMEM)
    for (int e = tid; e < 16 * 64; e += 128) {
        const int i = e >> 6, j = e & 63;
        float acc = 0.0f;
        #pragma unroll 8
        for (int k = 0; k < 64; ++k) acc = fmaf(sWin[i * 64 + k], sWf[k * 64 + j], acc);
        sWc[e] = acc;
    }
    // Wio[i][j] = sum_k W_in[i][k] * W_out[k][j]
    for (int e = tid; e < 16 * 16; e += 128) {
        const int i = e >> 4, j = e & 15;
        float acc = 0.0f;
        #pragma unroll 8
        for (int k = 0; k < 64; ++k) acc = fmaf(sWin[i * 64 + k], sWo[k * 16 + j], acc);
        sWio[e] = acc;
    }
    // bc = b_in @ Wf + bf ; bio = b_in @ W_out + b_out
    if (tid < 64) {
        float acc = bfv[tid];
        #pragma unroll 8
        for (int i = 0; i < 64; ++i) acc = fmaf(b_in[i], sWf[i * 64 + tid], acc);
        gbc[tid] = acc;
    } else if (tid < 80) {
        const int j = tid - 64;
        float acc = b_out[j];
        #pragma unroll 8
        for (int i = 0; i < 64; ++i) acc = fmaf(b_in[i], sWo[i * 16 + j], acc);
        gbio[j] = acc;
    }
    __syncthreads();

    if (w == 0) {
        #pragma unroll
        for (int nt = 0; nt < 8; ++nt) {
            const int col = nt * 8 + g;
            gWcTab[nt][lane] = make_frag(sWc[(lam * 2) * 64 + col],
                                         sWc[(lam * 2 + 1) * 64 + col],
                                         sWc[(lam * 2 + 8) * 64 + col],
                                         sWc[(lam * 2 + 9) * 64 + col]);
        }
    } else if (w == 1) {
        #pragma unroll
        for (int nt = 0; nt < 2; ++nt) {
            const int col = nt * 8 + g;
            gWioTab[nt][lane] = make_frag(sWio[(lam * 2) * 16 + col],
                                          sWio[(lam * 2 + 1) * 16 + col],
                                          sWio[(lam * 2 + 8) * 16 + col],
                                          sWio[(lam * 2 + 9) * 16 + col]);
        }
    } else if (w == 2) {
        #pragma unroll
        for (int kt = 0; kt < 4; ++kt)
            #pragma unroll
            for (int nt = 0; nt < 2; ++nt) {
                const int col = nt * 8 + g;
                const int kr  = kt * 16 + lam * 2;
                gWoutTab[kt][nt][lane] = make_frag(sWo[kr * 16 + col],
                                                   sWo[(kr + 1) * 16 + col],
                                                   sWo[(kr + 8) * 16 + col],
                                                   sWo[(kr + 9) * 16 + col]);
            }
    } else {
        #pragma unroll
        for (int kt = 0; kt < 4; ++kt)
            #pragma unroll
            for (int nt = 0; nt < 8; ++nt) {
                const int base = (kt * 16 + lam * 2) * 64 + nt * 8 + g;
                uint2 t;
                t.x = pack_h2(sWf[base], sWf[base + 64]);
                t.y = pack_h2(sWf[base + 8 * 64], sWf[base + 9 * 64]);
                gWfHi[kt][nt][lane] = t;
            }
    }
}

__global__ void __launch_bounds__(128, 2)
ode_rk4(const float* __restrict__ x, float* __restrict__ out) {
    __shared__ float sbc[64];
    __shared__ float sbio[16];

    const int tid  = threadIdx.x;
    const int lane = tid & 31;
    const int warp = tid >> 5;
    const int g    = lane >> 2;
    const int lam  = lane & 3;
    const long rowbase = (long)blockIdx.x * 64;
    const int r0 = warp * 16 + g;

    if (tid < 64) sbc[tid] = gbc[tid];
    if (tid < 16) sbio[tid] = gbio[tid];
    __syncthreads();

    // ---- x A-fragments (direct LDG.64), fp16 hi/lo split; live whole kernel ----
    const float* xr0 = x + (rowbase + r0) * 16 + 2 * lam;
    const float* xr8 = x + (rowbase + r0 + 8) * 16 + 2 * lam;
    float2 xa = *reinterpret_cast<const float2*>(xr0);
    float2 xb = *reinterpret_cast<const float2*>(xr8);
    float2 xc = *reinterpret_cast<const float2*>(xr0 + 8);
    float2 xd = *reinterpret_cast<const float2*>(xr8 + 8);
    uint32_t xh0 = pack_h2(xa.x, xa.y), xh1 = pack_h2(xb.x, xb.y);
    uint32_t xh2 = pack_h2(xc.x, xc.y), xh3 = pack_h2(xd.x, xd.y);
    uint32_t xl0 = pack_h2(xa.x - h_lo(xh0), xa.y - h_hi(xh0));
    uint32_t xl1 = pack_h2(xb.x - h_lo(xh1), xb.y - h_hi(xh1));
    uint32_t xl2 = pack_h2(xc.x - h_lo(xh2), xc.y - h_hi(xh2));
    uint32_t xl3 = pack_h2(xd.x - h_lo(xh3), xd.y - h_hi(xh3));

    // ---- z0 = x @ Wc + bc  (fused; 3 MMAs per n-tile) ----
    float z[8][4];
    #pragma unroll
    for (int nt = 0; nt < 8; ++nt) {
        uint4 wt = gWcTab[nt][lane];
        const float2 bb = *reinterpret_cast<const float2*>(&sbc[nt * 8 + lam * 2]);
        float c0 = bb.x, c1 = bb.y, c2 = bb.x, c3 = bb.y;
        mma_f16(c0, c1, c2, c3, xh0, xh1, xh2, xh3, wt.x, wt.y);
        mma_f16(c0, c1, c2, c3, xh0, xh1, xh2, xh3, wt.z, wt.w);
        mma_f16(c0, c1, c2, c3, xl0, xl1, xl2, xl3, wt.x, wt.y);
        z[nt][0] = c0; z[nt][1] = c1; z[nt][2] = c2; z[nt][3] = c3;
    }

    // ---- Wf hi fragments for the loop ----
    uint32_t Bh[4][8][2];
    #pragma unroll
    for (int kt = 0; kt < 4; ++kt)
        #pragma unroll
        for (int nt = 0; nt < 8; ++nt) {
            uint2 t = gWfHi[kt][nt][lane];
            Bh[kt][nt][0] = t.x;
            Bh[kt][nt][1] = t.y;
        }

    // ---- RK4 main loop (delta form); D accumulates y1 - y0 in fp32 ----
    const float DT   = 1.0f / 2.0f;
    const float DT6  = DT / 6.0f;
    const float CMID[3] = {DT * 0.5f, DT * 0.5f, DT};
    const float SW[3]   = {2.0f, 2.0f, 1.0f};

    float D[8][4];
    #pragma unroll
    for (int nt = 0; nt < 8; ++nt) {
        D[nt][0] = 0.f; D[nt][1] = 0.f; D[nt][2] = 0.f; D[nt][3] = 0.f;
    }

    float s[8][4];
    uint32_t a[4][4], an[4][4];

    #pragma unroll
    for (int step = 0; step < NSTEPS; ++step) {
        #pragma unroll
        for (int nt = 0; nt < 8; ++nt) {
            float k0 = tanh_fast(z[nt][0]);
            float k1 = tanh_fast(z[nt][1]);
            float k2 = tanh_fast(z[nt][2]);
            float k3 = tanh_fast(z[nt][3]);
            s[nt][0] = k0; s[nt][1] = k1; s[nt][2] = k2; s[nt][3] = k3;
            const int kt2 = nt >> 1, sl = (nt & 1) * 2;
            a[kt2][sl]     = pack_h2(CMID[0] * k0, CMID[0] * k1);
            a[kt2][sl + 1] = pack_h2(CMID[0] * k2, CMID[0] * k3);
        }
        #pragma unroll
        for (int e = 0; e < 3; ++e) {
            const float sw = SW[e];
            const float cm = (e < 2) ? CMID[e + 1] : 0.0f;
            #pragma unroll
            for (int nt = 0; nt < 8; ++nt) {
                float c0 = z[nt][0], c1 = z[nt][1], c2 = z[nt][2], c3 = z[nt][3];
                #pragma unroll
                for (int kt = 0; kt < 4; ++kt)
                    mma_f16(c0, c1, c2, c3,
                            a[kt][0], a[kt][1], a[kt][2], a[kt][3],
                            Bh[kt][nt][0], Bh[kt][nt][1]);
                c0 = tanh_fast(c0); c1 = tanh_fast(c1);
                c2 = tanh_fast(c2); c3 = tanh_fast(c3);
                s[nt][0] = fmaf(sw, c0, s[nt][0]);
                s[nt][1] = fmaf(sw, c1, s[nt][1]);
                s[nt][2] = fmaf(sw, c2, s[nt][2]);
                s[nt][3] = fmaf(sw, c3, s[nt][3]);
                if (e < 2) {
                    const int kt2 = nt >> 1, sl = (nt & 1) * 2;
                    an[kt2][sl]     = pack_h2(cm * c0, cm * c1);
                    an[kt2][sl + 1] = pack_h2(cm * c2, cm * c3);
                }
            }
            if (e < 2) {
                #pragma unroll
                for (int kt = 0; kt < 4; ++kt) {
                    a[kt][0] = an[kt][0]; a[kt][1] = an[kt][1];
                    a[kt][2] = an[kt][2]; a[kt][3] = an[kt][3];
                }
            }
        }
        #pragma unroll
        for (int nt = 0; nt < 8; ++nt) {
            float u0 = DT6 * s[nt][0], u1 = DT6 * s[nt][1];
            float u2 = DT6 * s[nt][2], u3 = DT6 * s[nt][3];
            D[nt][0] += u0; D[nt][1] += u1; D[nt][2] += u2; D[nt][3] += u3;
            const int kt2 = nt >> 1, sl = (nt & 1) * 2;
            a[kt2][sl]     = pack_h2(u0, u1);
            a[kt2][sl + 1] = pack_h2(u2, u3);
        }
        if (step < NSTEPS - 1) {
            #pragma unroll
            for (int nt = 0; nt < 8; ++nt) {
                #pragma unroll
                for (int kt = 0; kt < 4; ++kt)
                    mma_f16(z[nt][0], z[nt][1], z[nt][2], z[nt][3],
                            a[kt][0], a[kt][1], a[kt][2], a[kt][3],
                            Bh[kt][nt][0], Bh[kt][nt][1]);
            }
        }
    }

    // ---- readout: out = x@Wio + D@W_out + bio, direct STG ----
    {
        uint32_t ah[4][4], al[4][4];
        #pragma unroll
        for (int kt = 0; kt < 4; ++kt) {
            const int nA = 2 * kt, nB = 2 * kt + 1;
            ah[kt][0] = pack_h2(D[nA][0], D[nA][1]);
            ah[kt][1] = pack_h2(D[nA][2], D[nA][3]);
            ah[kt][2] = pack_h2(D[nB][0], D[nB][1]);
            ah[kt][3] = pack_h2(D[nB][2], D[nB][3]);
            al[kt][0] = pack_h2(D[nA][0] - h_lo(ah[kt][0]), D[nA][1] - h_hi(ah[kt][0]));
            al[kt][1] = pack_h2(D[nA][2] - h_lo(ah[kt][1]), D[nA][3] - h_hi(ah[kt][1]));
            al[kt][2] = pack_h2(D[nB][0] - h_lo(ah[kt][2]), D[nB][1] - h_hi(ah[kt][2]));
            al[kt][3] = pack_h2(D[nB][2] - h_lo(ah[kt][3]), D[nB][3] - h_hi(ah[kt][3]));
        }
        #pragma unroll
        for (int nt = 0; nt < 2; ++nt) {
            const float2 bb = *reinterpret_cast<const float2*>(&sbio[nt * 8 + lam * 2]);
            float c0 = bb.x, c1 = bb.y, c2 = bb.x, c3 = bb.y;
            uint4 wio = gWioTab[nt][lane];
            mma_f16(c0, c1, c2, c3, xh0, xh1, xh2, xh3, wio.x, wio.y);
            mma_f16(c0, c1, c2, c3, xh0, xh1, xh2, xh3, wio.z, wio.w);
            mma_f16(c0, c1, c2, c3, xl0, xl1, xl2, xl3, wio.x, wio.y);
            #pragma unroll
            for (int kt = 0; kt < 4; ++kt) {
                uint4 wt = gWoutTab[kt][nt][lane];
                mma_f16(c0, c1, c2, c3, ah[kt][0], ah[kt][1], ah[kt][2], ah[kt][3],
                        wt.x, wt.y);
                mma_f16(c0, c1, c2, c3, ah[kt][0], ah[kt][1], ah[kt][2], ah[kt][3],
                        wt.z, wt.w);
                mma_f16(c0, c1, c2, c3, al[kt][0], al[kt][1], al[kt][2], al[kt][3],
                        wt.x, wt.y);
            }
            float2* o0 = reinterpret_cast<float2*>(out + (rowbase + r0) * 16 + nt * 8 + 2 * lam);
            float2* o8 = reinterpret_cast<float2*>(out + (rowbase + r0 + 8) * 16 + nt * 8 + 2 * lam);
            *o0 = make_float2(c0, c1);
            *o8 = make_float2(c2, c3);
        }
    }
}

}  // namespace ode

extern "C" void kernel_launch(void* const* d_in, const int* in_sizes, int n_in,
                              void* d_out, int out_size) {
    const float* x     = (const float*)d_in[0];
    const float* W_in  = (const float*)d_in[1];
    const float* b_in  = (const float*)d_in[2];
    const float* Wf    = (const float*)d_in[3];
    const float* bfv   = (const float*)d_in[4];
    const float* W_out = (const float*)d_in[5];
    const float* b_out = (const float*)d_in[6];
    float* out = (float*)d_out;

    const int batch = in_sizes[0] / 16;
    const int grid  = batch / 64;
    ode::prep_tables<<<1, 128>>>(Wf, W_in, b_in, bfv, W_out, b_out);
    ode::ode_rk4<<<grid, 128>>>(x, out);
}